// round 11
// baseline (speedup 1.0000x reference)
#include <cuda_runtime.h>
#include <cuda_fp16.h>
#include <cstdint>

// ---------------------------------------------------------------------------
// GSMP_4879082848655 — R11: fp16 2-term split mma pipeline
//   Interleaved (hi,lo) uint2 A-buffer, ve k-remap (no duplicate copy),
//   BE=96/TPB=192 -> 3 blocks/SM (18 warps). dst-sorted seam-atomic scatter.
// ---------------------------------------------------------------------------

#define MAXN 100000
#define MAXE 1600000
#define BE   96
#define TPB  192

#define SAU2 84   // A-buffer row stride in uint2 (168 fp16 cols interleaved)

// edge kernel smem byte offsets
#define O_A   0                  // 96*84*8 = 64512
#define O_SK  64512
#define O_DST 64896
#define O_ORG 65280
#define SMEMB 65664

// node kernel smem
#define NSMEMB 86016             // 128*84*8

// frag tables (hi-only fp16 B fragments)
__device__ uint2 gF1[72 * 32];
__device__ uint2 gF2[102 * 32];
__device__ uint2 gF3[40 * 32];
__device__ uint2 gFr[40 * 32];

__device__ float    g_s1[MAXN * 32];
__device__ float    g_m4[MAXN * 32];
__device__ unsigned g_m2[MAXN * 32];
__device__ unsigned g_m3[MAXN * 32];
__device__ int      g_cnt[MAXN];
__device__ int      g_cur[MAXN];
__device__ int      g_part[128];
__device__ int4     g_pack[MAXE];   // {src, dst, orig, 0} in sorted order

// ---------------- helpers ----------------
__device__ __forceinline__ unsigned encf(float f) {
    unsigned u = __float_as_uint(f);
    return (u & 0x80000000u) ? ~u : (u | 0x80000000u);
}
__device__ __forceinline__ float decf(unsigned u) {
    u = (u & 0x80000000u) ? (u & 0x7FFFFFFFu) : ~u;
    return __uint_as_float(u);
}
// fp16 hi/lo split
__device__ __forceinline__ void split2(float a, float b, uint32_t& hi, uint32_t& lo) {
    __half2 hv = __floats2half2_rn(a, b);
    float ra = a - __half2float(__low2half(hv));
    float rb = b - __half2float(__high2half(hv));
    __half2 lv = __floats2half2_rn(ra, rb);
    hi = *reinterpret_cast<uint32_t*>(&hv);
    lo = *reinterpret_cast<uint32_t*>(&lv);
}
__device__ __forceinline__ void redadd2(float* p, float a, float b) {
    asm volatile("red.global.add.v2.f32 [%0], {%1,%2};" :: "l"(p), "f"(a), "f"(b) : "memory");
}
__device__ __forceinline__ void redmaxu(unsigned* p, unsigned v) {
    asm volatile("red.global.max.u32 [%0], %1;" :: "l"(p), "r"(v) : "memory");
}
__device__ __forceinline__ void redminu(unsigned* p, unsigned v) {
    asm volatile("red.global.min.u32 [%0], %1;" :: "l"(p), "r"(v) : "memory");
}
__device__ __forceinline__ void mma16816(float* c, const uint32_t* a, uint2 b) {
    asm volatile(
        "mma.sync.aligned.m16n8k16.row.col.f32.f16.f16.f32 "
        "{%0,%1,%2,%3}, {%4,%5,%6,%7}, {%8,%9}, {%0,%1,%2,%3};"
        : "+f"(c[0]), "+f"(c[1]), "+f"(c[2]), "+f"(c[3])
        : "r"(a[0]), "r"(a[1]), "r"(a[2]), "r"(a[3]), "r"(b.x), "r"(b.y));
}
__device__ __forceinline__ uint32_t pack_h(float w0, float w1) {
    __half2 v = __floats2half2_rn(w0, w1);
    return *reinterpret_cast<uint32_t*>(&v);
}
// load A fragment (hi+lo) for rows r0,r0+8 at column base col (even)
__device__ __forceinline__ void ldfragA(const uint2* A, int r0, int col,
                                        uint32_t* Ah, uint32_t* Al) {
    uint2 u0 = A[r0 * SAU2 + (col >> 1)];
    uint2 u1 = A[(r0 + 8) * SAU2 + (col >> 1)];
    uint2 u2 = A[r0 * SAU2 + ((col + 8) >> 1)];
    uint2 u3 = A[(r0 + 8) * SAU2 + ((col + 8) >> 1)];
    Ah[0] = u0.x; Al[0] = u0.y;
    Ah[1] = u1.x; Al[1] = u1.y;
    Ah[2] = u2.x; Al[2] = u2.y;
    Ah[3] = u3.x; Al[3] = u3.y;
}

// ---------------- prep: B fragments (hi-only fp16) in mma layout ----------------
__global__ void prep_kernel(const float* __restrict__ Wm1, const float* __restrict__ Wm2,
                            const float* __restrict__ We,  const float* __restrict__ Wr) {
    int t = blockIdx.x * blockDim.x + threadIdx.x;
    if (t >= 254 * 32) return;
    int lane = t & 31, f = t >> 5;
    int g = lane >> 2, tig = lane & 3;

    if (f < 72) {
        int ks = f % 6, nt = f / 6;
        int n = nt * 8 + g, k0 = ks * 16 + tig * 2;
        gF1[f * 32 + lane] = make_uint2(
            pack_h(Wm1[k0 * 96 + n], Wm1[(k0 + 1) * 96 + n]),
            pack_h(Wm1[(k0 + 8) * 96 + n], Wm1[(k0 + 9) * 96 + n]));
    } else if (f < 174) {
        int f2 = f - 72, ks = f2 % 6, nt = f2 / 6;
        int n = nt * 8 + g, k0 = ks * 16 + tig * 2;
        float w[4];
        #pragma unroll
        for (int i = 0; i < 4; i++) {
            int k = k0 + (i >> 1) * 8 + (i & 1);
            if (n < 128)       w[i] = Wm2[k * 129 + 1 + n];
            else if (n == 128) w[i] = Wm2[k * 129];
            else               w[i] = 0.f;
        }
        gF2[f2 * 32 + lane] = make_uint2(pack_h(w[0], w[1]), pack_h(w[2], w[3]));
    } else if (f < 214) {
        int f3 = f - 174, ks = f3 % 10, nt = f3 / 10;
        int n = nt * 8 + g, k0 = ks * 16 + tig * 2;
        gF3[f3 * 32 + lane] = make_uint2(
            pack_h(We[k0 * 32 + n], We[(k0 + 1) * 32 + n]),
            pack_h(We[(k0 + 8) * 32 + n], We[(k0 + 9) * 32 + n]));
    } else {
        int f4 = f - 214, ks = f4 % 10, nt = f4 / 10;
        int n = nt * 8 + g, k0 = ks * 16 + tig * 2;
        gFr[f4 * 32 + lane] = make_uint2(
            pack_h(Wr[k0 * 32 + n], Wr[(k0 + 1) * 32 + n]),
            pack_h(Wr[(k0 + 8) * 32 + n], Wr[(k0 + 9) * 32 + n]));
    }
}

__global__ void init_kernel(int N) {
    int i = blockIdx.x * blockDim.x + threadIdx.x;
    int tot = N * 8;
    if (i < tot) {
        float4 z = make_float4(0.f, 0.f, 0.f, 0.f);
        ((float4*)g_s1)[i] = z;
        ((float4*)g_m4)[i] = z;
        ((uint4*)g_m2)[i] = make_uint4(0u, 0u, 0u, 0u);
        ((uint4*)g_m3)[i] = make_uint4(~0u, ~0u, ~0u, ~0u);
    }
    if (i < N) g_cnt[i] = 0;
}

// ---------------- counting sort by dst ----------------
__global__ void hist_kernel(const int* __restrict__ dst, int E) {
    int i = blockIdx.x * blockDim.x + threadIdx.x;
    if (i < E) atomicAdd(&g_cnt[dst[i]], 1);
}

__global__ __launch_bounds__(1024)
void scanA_kernel(int N) {
    __shared__ int sh[1024];
    int b = blockIdx.x, t = threadIdx.x, i = b * 1024 + t;
    int v = (i < N) ? g_cnt[i] : 0;
    sh[t] = v;
    __syncthreads();
    #pragma unroll
    for (int d = 1; d < 1024; d <<= 1) {
        int x = (t >= d) ? sh[t - d] : 0;
        __syncthreads();
        sh[t] += x;
        __syncthreads();
    }
    if (i < N) g_cur[i] = sh[t] - v;
    if (t == 1023) g_part[b] = sh[t];
}

__global__ __launch_bounds__(128)
void scanB_kernel(int nb) {
    __shared__ int sh[128];
    int t = threadIdx.x;
    int v = (t < nb) ? g_part[t] : 0;
    sh[t] = v;
    __syncthreads();
    #pragma unroll
    for (int d = 1; d < 128; d <<= 1) {
        int x = (t >= d) ? sh[t - d] : 0;
        __syncthreads();
        sh[t] += x;
        __syncthreads();
    }
    if (t < nb) g_part[t] = sh[t] - v;
}

__global__ __launch_bounds__(1024)
void scanC_kernel(int N) {
    int i = blockIdx.x * 1024 + threadIdx.x;
    if (i < N) g_cur[i] += g_part[blockIdx.x];
}

__global__ void scat_kernel(const int* __restrict__ src, const int* __restrict__ dst, int E) {
    int i = blockIdx.x * blockDim.x + threadIdx.x;
    if (i < E) {
        int d = dst[i];
        int pos = atomicAdd(&g_cur[d], 1);
        g_pack[pos] = make_int4(src[i], d, i, 0);
    }
}

// ---------------- edge kernel ----------------
__global__ __launch_bounds__(TPB, 3)
void edge_kernel(const float* __restrict__ vc, const float* __restrict__ ve,
                 const float* __restrict__ bm1, const float* __restrict__ bm2,
                 const float* __restrict__ be, float* __restrict__ out_ve, int E)
{
    extern __shared__ char sm[];
    uint2* A   = (uint2*)(sm + O_A);
    float* sK  = (float*)(sm + O_SK);
    int*  sDst = (int*)(sm + O_DST);
    int*  sOrg = (int*)(sm + O_ORG);

    const int tid  = threadIdx.x;
    const int lane = tid & 31;
    const int wid  = tid >> 5;
    const int g    = lane >> 2;
    const int tig  = lane & 3;
    const int eBase = blockIdx.x * BE;

    // ---- gather (sorted order). Layout: vc_s 0..31, vc_d 32..63, ve 128..159
    {
        int e = tid >> 1, half = tid & 1;
        int ge = eBase + e;
        bool okR = ge < E;
        int gec = okR ? ge : (E - 1);
        int4 pk = g_pack[gec];            // {src, dst, orig, 0}
        if (half == 0) {
            sDst[e] = okR ? pk.y : -1;
            sOrg[e] = pk.z;
        }
        const float4* vs = (const float4*)(vc + (size_t)pk.x * 32);
        const float4* vd = (const float4*)(vc + (size_t)pk.y * 32);
        const float4* vv = (const float4*)(ve + (size_t)pk.z * 32);

        auto put4 = [&](int col, float4 v) {
            uint32_t h0, l0, h1, l1;
            split2(v.x, v.y, h0, l0);
            split2(v.z, v.w, h1, l1);
            // cols (col,col+1) and (col+2,col+3): two uint2 = one uint4 (16B aligned)
            *(uint4*)&A[e * SAU2 + (col >> 1)] = make_uint4(h0, l0, h1, l1);
        };
        if (half == 0) {
            #pragma unroll
            for (int q = 0; q < 8; q++) put4(q * 4, vs[q]);
            #pragma unroll
            for (int q = 0; q < 4; q++) put4(32 + q * 4, vd[q]);
        } else {
            #pragma unroll
            for (int q = 0; q < 8; q++) put4(128 + q * 4, vv[q]);
            #pragma unroll
            for (int q = 0; q < 4; q++) put4(48 + q * 4, vd[4 + q]);
        }
    }
    __syncthreads();   // only block-wide barrier

    const int r0 = wid * 16 + g;
    const int ge0 = eBase + r0, ge1 = ge0 + 8;
    const bool ok0 = ge0 < E, ok1 = ge1 < E;

    // ================= GEMM1: X -> H (cols 0..95; ve read from 128..159) ====
    {
        float c[12][4];
        #pragma unroll
        for (int nt = 0; nt < 12; nt++)
            #pragma unroll
            for (int i = 0; i < 4; i++) c[nt][i] = 0.f;

        #pragma unroll
        for (int ks = 0; ks < 6; ks++) {
            int kcol = (ks < 4) ? ks * 16 : 128 + (ks - 4) * 16;
            uint32_t Ah[4], Al[4];
            ldfragA(A, r0, kcol + tig * 2, Ah, Al);
            #pragma unroll
            for (int nt = 0; nt < 12; nt++) {
                uint2 bh = __ldg(&gF1[(nt * 6 + ks) * 32 + lane]);
                mma16816(c[nt], Ah, bh);
                mma16816(c[nt], Al, bh);
            }
        }
        __syncwarp();
        #pragma unroll
        for (int nt = 0; nt < 12; nt++) {
            int col = nt * 8 + tig * 2;
            float b0v = __ldg(&bm1[col]), b1v = __ldg(&bm1[col + 1]);
            float h00 = fmaxf(c[nt][0] + b0v, 0.f), h01 = fmaxf(c[nt][1] + b1v, 0.f);
            float h10 = fmaxf(c[nt][2] + b0v, 0.f), h11 = fmaxf(c[nt][3] + b1v, 0.f);
            uint32_t hi, lo;
            split2(h00, h01, hi, lo);
            A[r0 * SAU2 + (col >> 1)] = make_uint2(hi, lo);
            split2(h10, h11, hi, lo);
            A[(r0 + 8) * SAU2 + (col >> 1)] = make_uint2(hi, lo);
        }
    }
    __syncwarp();

    // ================= GEMM2: H -> F (cols 0..127) ==========================
    {
        float c[17][4];
        #pragma unroll
        for (int nt = 0; nt < 17; nt++)
            #pragma unroll
            for (int i = 0; i < 4; i++) c[nt][i] = 0.f;

        #pragma unroll
        for (int ks = 0; ks < 6; ks++) {
            uint32_t Ah[4], Al[4];
            ldfragA(A, r0, ks * 16 + tig * 2, Ah, Al);
            #pragma unroll
            for (int nt = 0; nt < 17; nt++) {
                uint2 bh = __ldg(&gF2[(nt * 6 + ks) * 32 + lane]);
                mma16816(c[nt], Ah, bh);
                mma16816(c[nt], Al, bh);
            }
        }
        if (tig == 0) {
            float b0v = __ldg(&bm2[0]);
            sK[r0]     = 1.f / (1.f + __expf(-(c[16][0] + b0v)));
            sK[r0 + 8] = 1.f / (1.f + __expf(-(c[16][2] + b0v)));
        }
        __syncwarp();
        float kg0 = sK[r0], kg1 = sK[r0 + 8];

        #pragma unroll
        for (int nt = 0; nt < 16; nt++) {
            int col = nt * 8 + tig * 2;
            float b0v = __ldg(&bm2[1 + col]), b1v = __ldg(&bm2[2 + col]);
            float f00 = (c[nt][0] + b0v) * kg0, f01 = (c[nt][1] + b1v) * kg0;
            float f10 = (c[nt][2] + b0v) * kg1, f11 = (c[nt][3] + b1v) * kg1;
            uint32_t hi, lo;
            split2(f00, f01, hi, lo);
            A[r0 * SAU2 + (col >> 1)] = make_uint2(hi, lo);
            split2(f10, f11, hi, lo);
            A[(r0 + 8) * SAU2 + (col >> 1)] = make_uint2(hi, lo);
        }
    }
    __syncwarp();   // F complete for this warp's 16 rows

    // ================= warp-local segmented reduction (sorted dst) =========
    {
        const int w16 = wid * 16;
        #pragma unroll
        for (int task = 0; task < 2; task++) {
            const int p  = lane + task * 32;
            const int c0 = 2 * p;
            const int grp = c0 >> 5;           // 0=sum,1=max,2=min,3=mean-sum
            float a0 = 0.f, a1 = 0.f;
            int cur = -1;
            bool firstSeg = true;

            auto flush = [&](bool atomic_) {
                if (cur < 0) return;
                size_t base = (size_t)cur * 32;
                if (grp == 0) {
                    if (atomic_) redadd2(&g_s1[base + c0], a0, a1);
                    else *(float2*)&g_s1[base + c0] = make_float2(a0, a1);
                } else if (grp == 1) {
                    unsigned e0 = encf(a0), e1 = encf(a1);
                    if (atomic_) { redmaxu(&g_m2[base + c0 - 32], e0);
                                   redmaxu(&g_m2[base + c0 - 31], e1); }
                    else { g_m2[base + c0 - 32] = e0; g_m2[base + c0 - 31] = e1; }
                } else if (grp == 2) {
                    unsigned e0 = encf(a0), e1 = encf(a1);
                    if (atomic_) { redminu(&g_m3[base + c0 - 64], e0);
                                   redminu(&g_m3[base + c0 - 63], e1); }
                    else { g_m3[base + c0 - 64] = e0; g_m3[base + c0 - 63] = e1; }
                } else {
                    if (atomic_) redadd2(&g_m4[base + c0 - 96], a0, a1);
                    else *(float2*)&g_m4[base + c0 - 96] = make_float2(a0, a1);
                }
            };

            #pragma unroll 4
            for (int r = w16; r < w16 + 16; r++) {
                int d = sDst[r];
                uint2 u = A[r * SAU2 + p];
                __half2 hh = *reinterpret_cast<__half2*>(&u.x);
                __half2 hl = *reinterpret_cast<__half2*>(&u.y);
                float f0 = __half2float(__low2half(hh))  + __half2float(__low2half(hl));
                float f1 = __half2float(__high2half(hh)) + __half2float(__high2half(hl));
                if (d != cur) {
                    flush(firstSeg);
                    if (cur >= 0) firstSeg = false;
                    cur = d;
                    a0 = f0; a1 = f1;
                } else if (grp == 1) {
                    a0 = fmaxf(a0, f0); a1 = fmaxf(a1, f1);
                } else if (grp == 2) {
                    a0 = fminf(a0, f0); a1 = fminf(a1, f1);
                } else {
                    a0 += f0; a1 += f1;
                }
            }
            flush(true);
        }
    }

    // ================= GEMM3: [F(0..127)|ve(128..159)] -> out_ve[orig] ======
    {
        float c[4][4];
        #pragma unroll
        for (int nt = 0; nt < 4; nt++)
            #pragma unroll
            for (int i = 0; i < 4; i++) c[nt][i] = 0.f;

        #pragma unroll
        for (int ks = 0; ks < 10; ks++) {
            int kcol = (ks < 8) ? ks * 16 : 128 + (ks - 8) * 16;
            uint32_t Ah[4], Al[4];
            ldfragA(A, r0, kcol + tig * 2, Ah, Al);
            #pragma unroll
            for (int nt = 0; nt < 4; nt++) {
                uint2 bh = __ldg(&gF3[(nt * 10 + ks) * 32 + lane]);
                mma16816(c[nt], Ah, bh);
                mma16816(c[nt], Al, bh);
            }
        }
        int o0 = sOrg[r0], o1 = sOrg[r0 + 8];
        #pragma unroll
        for (int nt = 0; nt < 4; nt++) {
            int col = nt * 8 + tig * 2;
            float b0v = __ldg(&be[col]), b1v = __ldg(&be[col + 1]);
            if (ok0) {
                float2 r = make_float2(c[nt][0] + b0v, c[nt][1] + b1v);
                *(float2*)(out_ve + (size_t)o0 * 32 + col) = r;
            }
            if (ok1) {
                float2 r = make_float2(c[nt][2] + b0v, c[nt][3] + b1v);
                *(float2*)(out_ve + (size_t)o1 * 32 + col) = r;
            }
        }
    }
}

// ================= node update via mma (interleaved layout) =================
__global__ __launch_bounds__(256, 2)
void node_mma_kernel(const float* __restrict__ vc, const float* __restrict__ br,
                     float* __restrict__ out_vc, int N)
{
    extern __shared__ char sm[];
    uint2* A = (uint2*)sm;
    const int tid  = threadIdx.x;
    const int lane = tid & 31;
    const int wid  = tid >> 5;
    const int g    = lane >> 2;
    const int tig  = lane & 3;
    const int nBase = blockIdx.x * 128;

    {
        int row = tid >> 1, half = tid & 1;
        int n = nBase + row;
        int nc = (n < N) ? n : (N - 1);
        float deg = (float)g_cnt[nc];
        bool has = deg > 0.f;
        float rdeg = 1.f / fmaxf(deg, 1.f);

        auto put4 = [&](int col, float4 v) {
            uint32_t h0, l0, h1, l1;
            split2(v.x, v.y, h0, l0);
            split2(v.z, v.w, h1, l1);
            *(uint4*)&A[row * SAU2 + (col >> 1)] = make_uint4(h0, l0, h1, l1);
        };
        for (int q = half; q < 40; q += 2) {
            float4 v;
            if (q < 8) {
                v = ((const float4*)(vc + (size_t)nc * 32))[q];
            } else if (q < 16) {
                v = ((const float4*)(g_s1 + (size_t)nc * 32))[q - 8];
            } else if (q < 24) {
                uint4 u = ((const uint4*)(g_m2 + (size_t)nc * 32))[q - 16];
                v = has ? make_float4(decf(u.x), decf(u.y), decf(u.z), decf(u.w))
                        : make_float4(0.f, 0.f, 0.f, 0.f);
            } else if (q < 32) {
                uint4 u = ((const uint4*)(g_m3 + (size_t)nc * 32))[q - 24];
                v = has ? make_float4(decf(u.x), decf(u.y), decf(u.z), decf(u.w))
                        : make_float4(0.f, 0.f, 0.f, 0.f);
            } else {
                float4 s = ((const float4*)(g_m4 + (size_t)nc * 32))[q - 32];
                v = make_float4(s.x * rdeg, s.y * rdeg, s.z * rdeg, s.w * rdeg);
            }
            put4(q * 4, v);
        }
    }
    __syncthreads();

    const int r0 = wid * 16 + g;
    const int n0 = nBase + r0, n1 = n0 + 8;

    float c[4][4];
    #pragma unroll
    for (int nt = 0; nt < 4; nt++)
        #pragma unroll
        for (int i = 0; i < 4; i++) c[nt][i] = 0.f;

    #pragma unroll
    for (int ks = 0; ks < 10; ks++) {
        uint32_t Ah[4], Al[4];
        ldfragA(A, r0, ks * 16 + tig * 2, Ah, Al);
        #pragma unroll
        for (int nt = 0; nt < 4; nt++) {
            uint2 bh = __ldg(&gFr[(nt * 10 + ks) * 32 + lane]);
            mma16816(c[nt], Ah, bh);
            mma16816(c[nt], Al, bh);
        }
    }
    #pragma unroll
    for (int nt = 0; nt < 4; nt++) {
        int col = nt * 8 + tig * 2;
        float b0v = __ldg(&br[col]), b1v = __ldg(&br[col + 1]);
        if (n0 < N) {
            float2 r = make_float2(c[nt][0] + b0v, c[nt][1] + b1v);
            *(float2*)(out_vc + (size_t)n0 * 32 + col) = r;
        }
        if (n1 < N) {
            float2 r = make_float2(c[nt][2] + b0v, c[nt][3] + b1v);
            *(float2*)(out_vc + (size_t)n1 * 32 + col) = r;
        }
    }
}

extern "C" void kernel_launch(void* const* d_in, const int* in_sizes, int n_in,
                              void* d_out, int out_size)
{
    const float* vc  = (const float*)d_in[0];
    const float* ve  = (const float*)d_in[1];
    const int*   src = (const int*)d_in[2];
    const int*   dst = (const int*)d_in[3];
    const float* Wm1 = (const float*)d_in[4];
    const float* bm1 = (const float*)d_in[5];
    const float* Wm2 = (const float*)d_in[6];
    const float* bm2 = (const float*)d_in[7];
    const float* Wr  = (const float*)d_in[8];
    const float* br  = (const float*)d_in[9];
    const float* We  = (const float*)d_in[10];
    const float* be  = (const float*)d_in[11];

    int N = in_sizes[0] / 32;
    int E = in_sizes[2];

    float* out_vc = (float*)d_out;
    float* out_ve = out_vc + (size_t)N * 32;

    int nb = (N + 1023) / 1024;

    cudaFuncSetAttribute(edge_kernel, cudaFuncAttributeMaxDynamicSharedMemorySize, SMEMB);
    cudaFuncSetAttribute(node_mma_kernel, cudaFuncAttributeMaxDynamicSharedMemorySize, NSMEMB);

    prep_kernel<<<(254 * 32 + 255) / 256, 256>>>(Wm1, Wm2, We, Wr);
    init_kernel<<<(N * 8 + 255) / 256, 256>>>(N);
    hist_kernel<<<(E + 255) / 256, 256>>>(dst, E);
    scanA_kernel<<<nb, 1024>>>(N);
    scanB_kernel<<<1, 128>>>(nb);
    scanC_kernel<<<nb, 1024>>>(N);
    scat_kernel<<<(E + 255) / 256, 256>>>(src, dst, E);
    edge_kernel<<<(E + BE - 1) / BE, TPB, SMEMB>>>(
        vc, ve, bm1, bm2, be, out_ve, E);
    node_mma_kernel<<<(N + 127) / 128, 256, NSMEMB>>>(vc, br, out_vc, N);
}

// round 12
// speedup vs baseline: 1.5199x; 1.5199x over previous
#include <cuda_runtime.h>
#include <cuda_fp16.h>
#include <cstdint>

// ---------------------------------------------------------------------------
// GSMP_4879082848655 — R12: R10 structure (fp16 2-term split, SA=168 split
// hi/lo buffers, TPB=256, 2 blk/SM) + int4-packed sort payload + ve k-remap.
// ---------------------------------------------------------------------------

#define MAXN 100000
#define MAXE 1600000
#define BE   128
#define TPB  256

#define SA 168   // A-buffer col stride (fp16 elems): conflict-free (84-word rows)

// edge kernel smem byte offsets
#define O_AHI 0
#define O_ALO 43008              // 128*168*2
#define O_SK  86016
#define O_DST 86528
#define O_ORG 87040
#define SMEMB 87552

// node kernel smem
#define ON_AHI 0
#define ON_ALO 43008
#define NSMEMB 86016

// frag tables (hi-only fp16 B fragments)
__device__ uint2 gF1[72 * 32];
__device__ uint2 gF2[102 * 32];
__device__ uint2 gF3[40 * 32];
__device__ uint2 gFr[40 * 32];

__device__ float    g_s1[MAXN * 32];
__device__ float    g_m4[MAXN * 32];
__device__ unsigned g_m2[MAXN * 32];
__device__ unsigned g_m3[MAXN * 32];
__device__ int      g_cnt[MAXN];
__device__ int      g_cur[MAXN];
__device__ int      g_part[128];
__device__ int4     g_pack[MAXE];   // {src, dst, orig, 0} sorted by dst

// ---------------- helpers ----------------
__device__ __forceinline__ unsigned encf(float f) {
    unsigned u = __float_as_uint(f);
    return (u & 0x80000000u) ? ~u : (u | 0x80000000u);
}
__device__ __forceinline__ float decf(unsigned u) {
    u = (u & 0x80000000u) ? (u & 0x7FFFFFFFu) : ~u;
    return __uint_as_float(u);
}
// fp16 hi/lo split: hi = rn(x), lo = rn(x - hi)
__device__ __forceinline__ void split2(float a, float b, uint32_t& hi, uint32_t& lo) {
    __half2 hv = __floats2half2_rn(a, b);
    float ra = a - __half2float(__low2half(hv));
    float rb = b - __half2float(__high2half(hv));
    __half2 lv = __floats2half2_rn(ra, rb);
    hi = *reinterpret_cast<uint32_t*>(&hv);
    lo = *reinterpret_cast<uint32_t*>(&lv);
}
__device__ __forceinline__ void redadd2(float* p, float a, float b) {
    asm volatile("red.global.add.v2.f32 [%0], {%1,%2};" :: "l"(p), "f"(a), "f"(b) : "memory");
}
__device__ __forceinline__ void redmaxu(unsigned* p, unsigned v) {
    asm volatile("red.global.max.u32 [%0], %1;" :: "l"(p), "r"(v) : "memory");
}
__device__ __forceinline__ void redminu(unsigned* p, unsigned v) {
    asm volatile("red.global.min.u32 [%0], %1;" :: "l"(p), "r"(v) : "memory");
}
__device__ __forceinline__ void mma16816(float* c, const uint32_t* a, uint2 b) {
    asm volatile(
        "mma.sync.aligned.m16n8k16.row.col.f32.f16.f16.f32 "
        "{%0,%1,%2,%3}, {%4,%5,%6,%7}, {%8,%9}, {%0,%1,%2,%3};"
        : "+f"(c[0]), "+f"(c[1]), "+f"(c[2]), "+f"(c[3])
        : "r"(a[0]), "r"(a[1]), "r"(a[2]), "r"(a[3]), "r"(b.x), "r"(b.y));
}
__device__ __forceinline__ uint32_t pack_h(float w0, float w1) {
    __half2 v = __floats2half2_rn(w0, w1);
    return *reinterpret_cast<uint32_t*>(&v);
}

// ---------------- prep: B fragments (hi-only fp16) in mma layout ----------------
__global__ void prep_kernel(const float* __restrict__ Wm1, const float* __restrict__ Wm2,
                            const float* __restrict__ We,  const float* __restrict__ Wr) {
    int t = blockIdx.x * blockDim.x + threadIdx.x;
    if (t >= 254 * 32) return;
    int lane = t & 31, f = t >> 5;
    int g = lane >> 2, tig = lane & 3;

    if (f < 72) {
        int ks = f % 6, nt = f / 6;
        int n = nt * 8 + g, k0 = ks * 16 + tig * 2;
        gF1[f * 32 + lane] = make_uint2(
            pack_h(Wm1[k0 * 96 + n], Wm1[(k0 + 1) * 96 + n]),
            pack_h(Wm1[(k0 + 8) * 96 + n], Wm1[(k0 + 9) * 96 + n]));
    } else if (f < 174) {
        int f2 = f - 72, ks = f2 % 6, nt = f2 / 6;
        int n = nt * 8 + g, k0 = ks * 16 + tig * 2;
        float w[4];
        #pragma unroll
        for (int i = 0; i < 4; i++) {
            int k = k0 + (i >> 1) * 8 + (i & 1);
            if (n < 128)       w[i] = Wm2[k * 129 + 1 + n];
            else if (n == 128) w[i] = Wm2[k * 129];
            else               w[i] = 0.f;
        }
        gF2[f2 * 32 + lane] = make_uint2(pack_h(w[0], w[1]), pack_h(w[2], w[3]));
    } else if (f < 214) {
        int f3 = f - 174, ks = f3 % 10, nt = f3 / 10;
        int n = nt * 8 + g, k0 = ks * 16 + tig * 2;
        gF3[f3 * 32 + lane] = make_uint2(
            pack_h(We[k0 * 32 + n], We[(k0 + 1) * 32 + n]),
            pack_h(We[(k0 + 8) * 32 + n], We[(k0 + 9) * 32 + n]));
    } else {
        int f4 = f - 214, ks = f4 % 10, nt = f4 / 10;
        int n = nt * 8 + g, k0 = ks * 16 + tig * 2;
        gFr[f4 * 32 + lane] = make_uint2(
            pack_h(Wr[k0 * 32 + n], Wr[(k0 + 1) * 32 + n]),
            pack_h(Wr[(k0 + 8) * 32 + n], Wr[(k0 + 9) * 32 + n]));
    }
}

__global__ void init_kernel(int N) {
    int i = blockIdx.x * blockDim.x + threadIdx.x;
    int tot = N * 8;
    if (i < tot) {
        float4 z = make_float4(0.f, 0.f, 0.f, 0.f);
        ((float4*)g_s1)[i] = z;
        ((float4*)g_m4)[i] = z;
        ((uint4*)g_m2)[i] = make_uint4(0u, 0u, 0u, 0u);
        ((uint4*)g_m3)[i] = make_uint4(~0u, ~0u, ~0u, ~0u);
    }
    if (i < N) g_cnt[i] = 0;
}

// ---------------- counting sort by dst ----------------
__global__ void hist_kernel(const int* __restrict__ dst, int E) {
    int i = blockIdx.x * blockDim.x + threadIdx.x;
    if (i < E) atomicAdd(&g_cnt[dst[i]], 1);
}

__global__ __launch_bounds__(1024)
void scanA_kernel(int N) {
    __shared__ int sh[1024];
    int b = blockIdx.x, t = threadIdx.x, i = b * 1024 + t;
    int v = (i < N) ? g_cnt[i] : 0;
    sh[t] = v;
    __syncthreads();
    #pragma unroll
    for (int d = 1; d < 1024; d <<= 1) {
        int x = (t >= d) ? sh[t - d] : 0;
        __syncthreads();
        sh[t] += x;
        __syncthreads();
    }
    if (i < N) g_cur[i] = sh[t] - v;
    if (t == 1023) g_part[b] = sh[t];
}

__global__ __launch_bounds__(128)
void scanB_kernel(int nb) {
    __shared__ int sh[128];
    int t = threadIdx.x;
    int v = (t < nb) ? g_part[t] : 0;
    sh[t] = v;
    __syncthreads();
    #pragma unroll
    for (int d = 1; d < 128; d <<= 1) {
        int x = (t >= d) ? sh[t - d] : 0;
        __syncthreads();
        sh[t] += x;
        __syncthreads();
    }
    if (t < nb) g_part[t] = sh[t] - v;
}

__global__ __launch_bounds__(1024)
void scanC_kernel(int N) {
    int i = blockIdx.x * 1024 + threadIdx.x;
    if (i < N) g_cur[i] += g_part[blockIdx.x];
}

__global__ void scat_kernel(const int* __restrict__ src, const int* __restrict__ dst, int E) {
    int i = blockIdx.x * blockDim.x + threadIdx.x;
    if (i < E) {
        int d = dst[i];
        int pos = atomicAdd(&g_cur[d], 1);
        g_pack[pos] = make_int4(src[i], d, i, 0);
    }
}

// ---------------- edge kernel ----------------
__global__ __launch_bounds__(TPB, 2)
void edge_kernel(const float* __restrict__ vc, const float* __restrict__ ve,
                 const float* __restrict__ bm1, const float* __restrict__ bm2,
                 const float* __restrict__ be, float* __restrict__ out_ve, int E)
{
    extern __shared__ char sm[];
    float* sK  = (float*)(sm + O_SK);
    int*  sDst = (int*)(sm + O_DST);
    int*  sOrg = (int*)(sm + O_ORG);

    const int tid  = threadIdx.x;
    const int lane = tid & 31;
    const int wid  = tid >> 5;
    const int g    = lane >> 2;
    const int tig  = lane & 3;
    const int eBase = blockIdx.x * BE;

    // ---- gather (sorted order): vc_s 0..31, vc_d 32..63, ve 128..159 ----
    {
        int e = tid >> 1, half = tid & 1;
        int ge = eBase + e;
        bool okR = ge < E;
        int gec = okR ? ge : (E - 1);
        int4 pk = g_pack[gec];            // {src, dst, orig, 0} — one LDG.128
        if (half == 0) {
            sDst[e] = okR ? pk.y : -1;
            sOrg[e] = pk.z;
        }
        const float4* vs = (const float4*)(vc + (size_t)pk.x * 32);
        const float4* vd = (const float4*)(vc + (size_t)pk.y * 32);
        const float4* vv = (const float4*)(ve + (size_t)pk.z * 32);

        auto put4 = [&](int col, float4 v) {
            uint32_t h0, l0, h1, l1;
            split2(v.x, v.y, h0, l0);
            split2(v.z, v.w, h1, l1);
            int idx = (e * SA + col) * 2;
            *(uint2*)(sm + O_AHI + idx) = make_uint2(h0, h1);
            *(uint2*)(sm + O_ALO + idx) = make_uint2(l0, l1);
        };
        if (half == 0) {
            #pragma unroll
            for (int q = 0; q < 8; q++) put4(q * 4, vs[q]);
            #pragma unroll
            for (int q = 0; q < 4; q++) put4(32 + q * 4, vd[q]);
        } else {
            #pragma unroll
            for (int q = 0; q < 8; q++) put4(128 + q * 4, vv[q]);   // ve: single copy
            #pragma unroll
            for (int q = 0; q < 4; q++) put4(48 + q * 4, vd[4 + q]);
        }
    }
    __syncthreads();   // only block-wide barrier

    const int r0 = wid * 16 + g;
    const int ge0 = eBase + r0, ge1 = ge0 + 8;
    const bool ok0 = ge0 < E, ok1 = ge1 < E;

    // ================= GEMM1: X -> H (cols 0..95; ve read via k-remap) ======
    {
        float c[12][4];
        #pragma unroll
        for (int nt = 0; nt < 12; nt++)
            #pragma unroll
            for (int i = 0; i < 4; i++) c[nt][i] = 0.f;

        #pragma unroll
        for (int ks = 0; ks < 6; ks++) {
            int kcol = (ks < 4) ? ks * 16 : 128 + (ks - 4) * 16;  // ve at 128..159
            int b0 = (r0 * SA + kcol + tig * 2) * 2;
            int b1 = ((r0 + 8) * SA + kcol + tig * 2) * 2;
            uint32_t Ah[4], Al[4];
            Ah[0] = *(uint32_t*)(sm + O_AHI + b0);
            Ah[1] = *(uint32_t*)(sm + O_AHI + b1);
            Ah[2] = *(uint32_t*)(sm + O_AHI + b0 + 16);
            Ah[3] = *(uint32_t*)(sm + O_AHI + b1 + 16);
            Al[0] = *(uint32_t*)(sm + O_ALO + b0);
            Al[1] = *(uint32_t*)(sm + O_ALO + b1);
            Al[2] = *(uint32_t*)(sm + O_ALO + b0 + 16);
            Al[3] = *(uint32_t*)(sm + O_ALO + b1 + 16);
            #pragma unroll
            for (int nt = 0; nt < 12; nt++) {
                uint2 bh = __ldg(&gF1[(nt * 6 + ks) * 32 + lane]);
                mma16816(c[nt], Ah, bh);
                mma16816(c[nt], Al, bh);
            }
        }
        __syncwarp();
        #pragma unroll
        for (int nt = 0; nt < 12; nt++) {
            int col = nt * 8 + tig * 2;
            float b0v = __ldg(&bm1[col]), b1v = __ldg(&bm1[col + 1]);
            float h00 = fmaxf(c[nt][0] + b0v, 0.f), h01 = fmaxf(c[nt][1] + b1v, 0.f);
            float h10 = fmaxf(c[nt][2] + b0v, 0.f), h11 = fmaxf(c[nt][3] + b1v, 0.f);
            uint32_t hi, lo;
            split2(h00, h01, hi, lo);
            int i0 = (r0 * SA + col) * 2;
            *(uint32_t*)(sm + O_AHI + i0) = hi;
            *(uint32_t*)(sm + O_ALO + i0) = lo;
            split2(h10, h11, hi, lo);
            int i1 = ((r0 + 8) * SA + col) * 2;
            *(uint32_t*)(sm + O_AHI + i1) = hi;
            *(uint32_t*)(sm + O_ALO + i1) = lo;
        }
    }
    __syncwarp();

    // ================= GEMM2: H -> F (cols 0..127) ==========================
    {
        float c[17][4];
        #pragma unroll
        for (int nt = 0; nt < 17; nt++)
            #pragma unroll
            for (int i = 0; i < 4; i++) c[nt][i] = 0.f;

        #pragma unroll
        for (int ks = 0; ks < 6; ks++) {
            int b0 = (r0 * SA + ks * 16 + tig * 2) * 2;
            int b1 = ((r0 + 8) * SA + ks * 16 + tig * 2) * 2;
            uint32_t Ah[4], Al[4];
            Ah[0] = *(uint32_t*)(sm + O_AHI + b0);
            Ah[1] = *(uint32_t*)(sm + O_AHI + b1);
            Ah[2] = *(uint32_t*)(sm + O_AHI + b0 + 16);
            Ah[3] = *(uint32_t*)(sm + O_AHI + b1 + 16);
            Al[0] = *(uint32_t*)(sm + O_ALO + b0);
            Al[1] = *(uint32_t*)(sm + O_ALO + b1);
            Al[2] = *(uint32_t*)(sm + O_ALO + b0 + 16);
            Al[3] = *(uint32_t*)(sm + O_ALO + b1 + 16);
            #pragma unroll
            for (int nt = 0; nt < 17; nt++) {
                uint2 bh = __ldg(&gF2[(nt * 6 + ks) * 32 + lane]);
                mma16816(c[nt], Ah, bh);
                mma16816(c[nt], Al, bh);
            }
        }
        if (tig == 0) {
            float b0v = __ldg(&bm2[0]);
            sK[r0]     = 1.f / (1.f + __expf(-(c[16][0] + b0v)));
            sK[r0 + 8] = 1.f / (1.f + __expf(-(c[16][2] + b0v)));
        }
        __syncwarp();
        float kg0 = sK[r0], kg1 = sK[r0 + 8];

        #pragma unroll
        for (int nt = 0; nt < 16; nt++) {
            int col = nt * 8 + tig * 2;
            float b0v = __ldg(&bm2[1 + col]), b1v = __ldg(&bm2[2 + col]);
            float f00 = (c[nt][0] + b0v) * kg0, f01 = (c[nt][1] + b1v) * kg0;
            float f10 = (c[nt][2] + b0v) * kg1, f11 = (c[nt][3] + b1v) * kg1;
            uint32_t hi, lo;
            split2(f00, f01, hi, lo);
            int i0 = (r0 * SA + col) * 2;
            *(uint32_t*)(sm + O_AHI + i0) = hi;
            *(uint32_t*)(sm + O_ALO + i0) = lo;
            split2(f10, f11, hi, lo);
            int i1 = ((r0 + 8) * SA + col) * 2;
            *(uint32_t*)(sm + O_AHI + i1) = hi;
            *(uint32_t*)(sm + O_ALO + i1) = lo;
        }
    }
    __syncwarp();   // F complete for this warp's 16 rows

    // ================= warp-local segmented reduction (sorted dst) =========
    {
        const int w16 = wid * 16;
        #pragma unroll
        for (int task = 0; task < 2; task++) {
            const int p  = lane + task * 32;
            const int c0 = 2 * p;
            const int grp = c0 >> 5;           // 0=sum,1=max,2=min,3=mean-sum
            float a0 = 0.f, a1 = 0.f;
            int cur = -1;
            bool firstSeg = true;

            auto flush = [&](bool atomic_) {
                if (cur < 0) return;
                size_t base = (size_t)cur * 32;
                if (grp == 0) {
                    if (atomic_) redadd2(&g_s1[base + c0], a0, a1);
                    else *(float2*)&g_s1[base + c0] = make_float2(a0, a1);
                } else if (grp == 1) {
                    unsigned e0 = encf(a0), e1 = encf(a1);
                    if (atomic_) { redmaxu(&g_m2[base + c0 - 32], e0);
                                   redmaxu(&g_m2[base + c0 - 31], e1); }
                    else { g_m2[base + c0 - 32] = e0; g_m2[base + c0 - 31] = e1; }
                } else if (grp == 2) {
                    unsigned e0 = encf(a0), e1 = encf(a1);
                    if (atomic_) { redminu(&g_m3[base + c0 - 64], e0);
                                   redminu(&g_m3[base + c0 - 63], e1); }
                    else { g_m3[base + c0 - 64] = e0; g_m3[base + c0 - 63] = e1; }
                } else {
                    if (atomic_) redadd2(&g_m4[base + c0 - 96], a0, a1);
                    else *(float2*)&g_m4[base + c0 - 96] = make_float2(a0, a1);
                }
            };

            #pragma unroll 4
            for (int r = w16; r < w16 + 16; r++) {
                int d = sDst[r];
                uint32_t uh = *(const uint32_t*)(sm + O_AHI + (r * SA + c0) * 2);
                uint32_t ul = *(const uint32_t*)(sm + O_ALO + (r * SA + c0) * 2);
                __half2 hh = *reinterpret_cast<__half2*>(&uh);
                __half2 hl = *reinterpret_cast<__half2*>(&ul);
                float f0 = __half2float(__low2half(hh))  + __half2float(__low2half(hl));
                float f1 = __half2float(__high2half(hh)) + __half2float(__high2half(hl));
                if (d != cur) {
                    flush(firstSeg);
                    if (cur >= 0) firstSeg = false;
                    cur = d;
                    a0 = f0; a1 = f1;
                } else if (grp == 1) {
                    a0 = fmaxf(a0, f0); a1 = fmaxf(a1, f1);
                } else if (grp == 2) {
                    a0 = fminf(a0, f0); a1 = fminf(a1, f1);
                } else {
                    a0 += f0; a1 += f1;
                }
            }
            flush(true);
        }
    }

    // ================= GEMM3: [F(0..127)|ve(128..159)] -> out_ve[orig] ======
    {
        float c[4][4];
        #pragma unroll
        for (int nt = 0; nt < 4; nt++)
            #pragma unroll
            for (int i = 0; i < 4; i++) c[nt][i] = 0.f;

        #pragma unroll
        for (int ks = 0; ks < 10; ks++) {
            int b0 = (r0 * SA + ks * 16 + tig * 2) * 2;
            int b1 = ((r0 + 8) * SA + ks * 16 + tig * 2) * 2;
            uint32_t Ah[4], Al[4];
            Ah[0] = *(uint32_t*)(sm + O_AHI + b0);
            Ah[1] = *(uint32_t*)(sm + O_AHI + b1);
            Ah[2] = *(uint32_t*)(sm + O_AHI + b0 + 16);
            Ah[3] = *(uint32_t*)(sm + O_AHI + b1 + 16);
            Al[0] = *(uint32_t*)(sm + O_ALO + b0);
            Al[1] = *(uint32_t*)(sm + O_ALO + b1);
            Al[2] = *(uint32_t*)(sm + O_ALO + b0 + 16);
            Al[3] = *(uint32_t*)(sm + O_ALO + b1 + 16);
            #pragma unroll
            for (int nt = 0; nt < 4; nt++) {
                uint2 bh = __ldg(&gF3[(nt * 10 + ks) * 32 + lane]);
                mma16816(c[nt], Ah, bh);
                mma16816(c[nt], Al, bh);
            }
        }
        int o0 = sOrg[r0], o1 = sOrg[r0 + 8];
        #pragma unroll
        for (int nt = 0; nt < 4; nt++) {
            int col = nt * 8 + tig * 2;
            float b0v = __ldg(&be[col]), b1v = __ldg(&be[col + 1]);
            if (ok0) {
                float2 r = make_float2(c[nt][0] + b0v, c[nt][1] + b1v);
                *(float2*)(out_ve + (size_t)o0 * 32 + col) = r;
            }
            if (ok1) {
                float2 r = make_float2(c[nt][2] + b0v, c[nt][3] + b1v);
                *(float2*)(out_ve + (size_t)o1 * 32 + col) = r;
            }
        }
    }
}

// ================= node update via mma =================
__global__ __launch_bounds__(TPB, 2)
void node_mma_kernel(const float* __restrict__ vc, const float* __restrict__ br,
                     float* __restrict__ out_vc, int N)
{
    extern __shared__ char sm[];
    const int tid  = threadIdx.x;
    const int lane = tid & 31;
    const int wid  = tid >> 5;
    const int g    = lane >> 2;
    const int tig  = lane & 3;
    const int nBase = blockIdx.x * 128;

    {
        int row = tid >> 1, half = tid & 1;
        int n = nBase + row;
        int nc = (n < N) ? n : (N - 1);
        float deg = (float)g_cnt[nc];
        bool has = deg > 0.f;
        float rdeg = 1.f / fmaxf(deg, 1.f);

        auto put4 = [&](int col, float4 v) {
            uint32_t h0, l0, h1, l1;
            split2(v.x, v.y, h0, l0);
            split2(v.z, v.w, h1, l1);
            int idx = (row * SA + col) * 2;
            *(uint2*)(sm + ON_AHI + idx) = make_uint2(h0, h1);
            *(uint2*)(sm + ON_ALO + idx) = make_uint2(l0, l1);
        };
        for (int q = half; q < 40; q += 2) {
            float4 v;
            if (q < 8) {
                v = ((const float4*)(vc + (size_t)nc * 32))[q];
            } else if (q < 16) {
                v = ((const float4*)(g_s1 + (size_t)nc * 32))[q - 8];
            } else if (q < 24) {
                uint4 u = ((const uint4*)(g_m2 + (size_t)nc * 32))[q - 16];
                v = has ? make_float4(decf(u.x), decf(u.y), decf(u.z), decf(u.w))
                        : make_float4(0.f, 0.f, 0.f, 0.f);
            } else if (q < 32) {
                uint4 u = ((const uint4*)(g_m3 + (size_t)nc * 32))[q - 24];
                v = has ? make_float4(decf(u.x), decf(u.y), decf(u.z), decf(u.w))
                        : make_float4(0.f, 0.f, 0.f, 0.f);
            } else {
                float4 s = ((const float4*)(g_m4 + (size_t)nc * 32))[q - 32];
                v = make_float4(s.x * rdeg, s.y * rdeg, s.z * rdeg, s.w * rdeg);
            }
            put4(q * 4, v);
        }
    }
    __syncthreads();

    const int r0 = wid * 16 + g;
    const int n0 = nBase + r0, n1 = n0 + 8;

    float c[4][4];
    #pragma unroll
    for (int nt = 0; nt < 4; nt++)
        #pragma unroll
        for (int i = 0; i < 4; i++) c[nt][i] = 0.f;

    #pragma unroll
    for (int ks = 0; ks < 10; ks++) {
        int b0 = (r0 * SA + ks * 16 + tig * 2) * 2;
        int b1 = ((r0 + 8) * SA + ks * 16 + tig * 2) * 2;
        uint32_t Ah[4], Al[4];
        Ah[0] = *(uint32_t*)(sm + ON_AHI + b0);
        Ah[1] = *(uint32_t*)(sm + ON_AHI + b1);
        Ah[2] = *(uint32_t*)(sm + ON_AHI + b0 + 16);
        Ah[3] = *(uint32_t*)(sm + ON_AHI + b1 + 16);
        Al[0] = *(uint32_t*)(sm + ON_ALO + b0);
        Al[1] = *(uint32_t*)(sm + ON_ALO + b1);
        Al[2] = *(uint32_t*)(sm + ON_ALO + b0 + 16);
        Al[3] = *(uint32_t*)(sm + ON_ALO + b1 + 16);
        #pragma unroll
        for (int nt = 0; nt < 4; nt++) {
            uint2 bh = __ldg(&gFr[(nt * 10 + ks) * 32 + lane]);
            mma16816(c[nt], Ah, bh);
            mma16816(c[nt], Al, bh);
        }
    }
    #pragma unroll
    for (int nt = 0; nt < 4; nt++) {
        int col = nt * 8 + tig * 2;
        float b0v = __ldg(&br[col]), b1v = __ldg(&br[col + 1]);
        if (n0 < N) {
            float2 r = make_float2(c[nt][0] + b0v, c[nt][1] + b1v);
            *(float2*)(out_vc + (size_t)n0 * 32 + col) = r;
        }
        if (n1 < N) {
            float2 r = make_float2(c[nt][2] + b0v, c[nt][3] + b1v);
            *(float2*)(out_vc + (size_t)n1 * 32 + col) = r;
        }
    }
}

extern "C" void kernel_launch(void* const* d_in, const int* in_sizes, int n_in,
                              void* d_out, int out_size)
{
    const float* vc  = (const float*)d_in[0];
    const float* ve  = (const float*)d_in[1];
    const int*   src = (const int*)d_in[2];
    const int*   dst = (const int*)d_in[3];
    const float* Wm1 = (const float*)d_in[4];
    const float* bm1 = (const float*)d_in[5];
    const float* Wm2 = (const float*)d_in[6];
    const float* bm2 = (const float*)d_in[7];
    const float* Wr  = (const float*)d_in[8];
    const float* br  = (const float*)d_in[9];
    const float* We  = (const float*)d_in[10];
    const float* be  = (const float*)d_in[11];

    int N = in_sizes[0] / 32;
    int E = in_sizes[2];

    float* out_vc = (float*)d_out;
    float* out_ve = out_vc + (size_t)N * 32;

    int nb = (N + 1023) / 1024;

    cudaFuncSetAttribute(edge_kernel, cudaFuncAttributeMaxDynamicSharedMemorySize, SMEMB);
    cudaFuncSetAttribute(node_mma_kernel, cudaFuncAttributeMaxDynamicSharedMemorySize, NSMEMB);

    prep_kernel<<<(254 * 32 + 255) / 256, 256>>>(Wm1, Wm2, We, Wr);
    init_kernel<<<(N * 8 + 255) / 256, 256>>>(N);
    hist_kernel<<<(E + 255) / 256, 256>>>(dst, E);
    scanA_kernel<<<nb, 1024>>>(N);
    scanB_kernel<<<1, 128>>>(nb);
    scanC_kernel<<<nb, 1024>>>(N);
    scat_kernel<<<(E + 255) / 256, 256>>>(src, dst, E);
    edge_kernel<<<(E + BE - 1) / BE, TPB, SMEMB>>>(
        vc, ve, bm1, bm2, be, out_ve, E);
    node_mma_kernel<<<(N + 127) / 128, TPB, NSMEMB>>>(vc, br, out_vc, N);
}

// round 15
// speedup vs baseline: 1.8246x; 1.2005x over previous
#include <cuda_runtime.h>
#include <cuda_fp16.h>
#include <cstdint>

// ---------------------------------------------------------------------------
// GSMP_4879082848655 — R13: pure fp16 single-term mma pipeline
//   (R12 minus the A-lo split: 214 MMAs/warp, half the smem/LDS/convert work)
// ---------------------------------------------------------------------------

#define MAXN 100000
#define MAXE 1600000
#define BE   128
#define TPB  256

#define SA 168   // A-buffer col stride (fp16 elems): conflict-free (84-word rows)

// edge kernel smem byte offsets
#define O_A   0                  // 128*168*2 = 43008
#define O_SK  43008
#define O_DST 43520
#define O_ORG 44032
#define SMEMB 44544

// node kernel smem
#define NSMEMB 43008

// frag tables (fp16 B fragments)
__device__ uint2 gF1[72 * 32];
__device__ uint2 gF2[102 * 32];
__device__ uint2 gF3[40 * 32];
__device__ uint2 gFr[40 * 32];

__device__ float    g_s1[MAXN * 32];
__device__ float    g_m4[MAXN * 32];
__device__ unsigned g_m2[MAXN * 32];
__device__ unsigned g_m3[MAXN * 32];
__device__ int      g_cnt[MAXN];
__device__ int      g_cur[MAXN];
__device__ int      g_part[128];
__device__ int4     g_pack[MAXE];   // {src, dst, orig, 0} sorted by dst

// ---------------- helpers ----------------
__device__ __forceinline__ unsigned encf(float f) {
    unsigned u = __float_as_uint(f);
    return (u & 0x80000000u) ? ~u : (u | 0x80000000u);
}
__device__ __forceinline__ float decf(unsigned u) {
    u = (u & 0x80000000u) ? (u & 0x7FFFFFFFu) : ~u;
    return __uint_as_float(u);
}
__device__ __forceinline__ uint32_t pack_h(float a, float b) {
    __half2 v = __floats2half2_rn(a, b);
    return *reinterpret_cast<uint32_t*>(&v);
}
__device__ __forceinline__ void redadd2(float* p, float a, float b) {
    asm volatile("red.global.add.v2.f32 [%0], {%1,%2};" :: "l"(p), "f"(a), "f"(b) : "memory");
}
__device__ __forceinline__ void redmaxu(unsigned* p, unsigned v) {
    asm volatile("red.global.max.u32 [%0], %1;" :: "l"(p), "r"(v) : "memory");
}
__device__ __forceinline__ void redminu(unsigned* p, unsigned v) {
    asm volatile("red.global.min.u32 [%0], %1;" :: "l"(p), "r"(v) : "memory");
}
__device__ __forceinline__ void mma16816(float* c, const uint32_t* a, uint2 b) {
    asm volatile(
        "mma.sync.aligned.m16n8k16.row.col.f32.f16.f16.f32 "
        "{%0,%1,%2,%3}, {%4,%5,%6,%7}, {%8,%9}, {%0,%1,%2,%3};"
        : "+f"(c[0]), "+f"(c[1]), "+f"(c[2]), "+f"(c[3])
        : "r"(a[0]), "r"(a[1]), "r"(a[2]), "r"(a[3]), "r"(b.x), "r"(b.y));
}

// ---------------- prep: B fragments (fp16) in mma layout ----------------
__global__ void prep_kernel(const float* __restrict__ Wm1, const float* __restrict__ Wm2,
                            const float* __restrict__ We,  const float* __restrict__ Wr) {
    int t = blockIdx.x * blockDim.x + threadIdx.x;
    if (t >= 254 * 32) return;
    int lane = t & 31, f = t >> 5;
    int g = lane >> 2, tig = lane & 3;

    if (f < 72) {
        int ks = f % 6, nt = f / 6;
        int n = nt * 8 + g, k0 = ks * 16 + tig * 2;
        gF1[f * 32 + lane] = make_uint2(
            pack_h(Wm1[k0 * 96 + n], Wm1[(k0 + 1) * 96 + n]),
            pack_h(Wm1[(k0 + 8) * 96 + n], Wm1[(k0 + 9) * 96 + n]));
    } else if (f < 174) {
        int f2 = f - 72, ks = f2 % 6, nt = f2 / 6;
        int n = nt * 8 + g, k0 = ks * 16 + tig * 2;
        float w[4];
        #pragma unroll
        for (int i = 0; i < 4; i++) {
            int k = k0 + (i >> 1) * 8 + (i & 1);
            if (n < 128)       w[i] = Wm2[k * 129 + 1 + n];
            else if (n == 128) w[i] = Wm2[k * 129];
            else               w[i] = 0.f;
        }
        gF2[f2 * 32 + lane] = make_uint2(pack_h(w[0], w[1]), pack_h(w[2], w[3]));
    } else if (f < 214) {
        int f3 = f - 174, ks = f3 % 10, nt = f3 / 10;
        int n = nt * 8 + g, k0 = ks * 16 + tig * 2;
        gF3[f3 * 32 + lane] = make_uint2(
            pack_h(We[k0 * 32 + n], We[(k0 + 1) * 32 + n]),
            pack_h(We[(k0 + 8) * 32 + n], We[(k0 + 9) * 32 + n]));
    } else {
        int f4 = f - 214, ks = f4 % 10, nt = f4 / 10;
        int n = nt * 8 + g, k0 = ks * 16 + tig * 2;
        gFr[f4 * 32 + lane] = make_uint2(
            pack_h(Wr[k0 * 32 + n], Wr[(k0 + 1) * 32 + n]),
            pack_h(Wr[(k0 + 8) * 32 + n], Wr[(k0 + 9) * 32 + n]));
    }
}

__global__ void init_kernel(int N) {
    int i = blockIdx.x * blockDim.x + threadIdx.x;
    int tot = N * 8;
    if (i < tot) {
        float4 z = make_float4(0.f, 0.f, 0.f, 0.f);
        ((float4*)g_s1)[i] = z;
        ((float4*)g_m4)[i] = z;
        ((uint4*)g_m2)[i] = make_uint4(0u, 0u, 0u, 0u);
        ((uint4*)g_m3)[i] = make_uint4(~0u, ~0u, ~0u, ~0u);
    }
    if (i < N) g_cnt[i] = 0;
}

// ---------------- counting sort by dst ----------------
__global__ void hist_kernel(const int* __restrict__ dst, int E) {
    int i = blockIdx.x * blockDim.x + threadIdx.x;
    if (i < E) atomicAdd(&g_cnt[dst[i]], 1);
}

__global__ __launch_bounds__(1024)
void scanA_kernel(int N) {
    __shared__ int sh[1024];
    int b = blockIdx.x, t = threadIdx.x, i = b * 1024 + t;
    int v = (i < N) ? g_cnt[i] : 0;
    sh[t] = v;
    __syncthreads();
    #pragma unroll
    for (int d = 1; d < 1024; d <<= 1) {
        int x = (t >= d) ? sh[t - d] : 0;
        __syncthreads();
        sh[t] += x;
        __syncthreads();
    }
    if (i < N) g_cur[i] = sh[t] - v;
    if (t == 1023) g_part[b] = sh[t];
}

__global__ __launch_bounds__(128)
void scanB_kernel(int nb) {
    __shared__ int sh[128];
    int t = threadIdx.x;
    int v = (t < nb) ? g_part[t] : 0;
    sh[t] = v;
    __syncthreads();
    #pragma unroll
    for (int d = 1; d < 128; d <<= 1) {
        int x = (t >= d) ? sh[t - d] : 0;
        __syncthreads();
        sh[t] += x;
        __syncthreads();
    }
    if (t < nb) g_part[t] = sh[t] - v;
}

__global__ __launch_bounds__(1024)
void scanC_kernel(int N) {
    int i = blockIdx.x * 1024 + threadIdx.x;
    if (i < N) g_cur[i] += g_part[blockIdx.x];
}

__global__ void scat_kernel(const int* __restrict__ src, const int* __restrict__ dst, int E) {
    int i = blockIdx.x * blockDim.x + threadIdx.x;
    if (i < E) {
        int d = dst[i];
        int pos = atomicAdd(&g_cur[d], 1);
        g_pack[pos] = make_int4(src[i], d, i, 0);
    }
}

// ---------------- edge kernel ----------------
__global__ __launch_bounds__(TPB, 2)
void edge_kernel(const float* __restrict__ vc, const float* __restrict__ ve,
                 const float* __restrict__ bm1, const float* __restrict__ bm2,
                 const float* __restrict__ be, float* __restrict__ out_ve, int E)
{
    extern __shared__ char sm[];
    float* sK  = (float*)(sm + O_SK);
    int*  sDst = (int*)(sm + O_DST);
    int*  sOrg = (int*)(sm + O_ORG);

    const int tid  = threadIdx.x;
    const int lane = tid & 31;
    const int wid  = tid >> 5;
    const int g    = lane >> 2;
    const int tig  = lane & 3;
    const int eBase = blockIdx.x * BE;

    // ---- gather (sorted order): vc_s 0..31, vc_d 32..63, ve 128..159 ----
    {
        int e = tid >> 1, half = tid & 1;
        int ge = eBase + e;
        bool okR = ge < E;
        int gec = okR ? ge : (E - 1);
        int4 pk = g_pack[gec];            // one LDG.128
        if (half == 0) {
            sDst[e] = okR ? pk.y : -1;
            sOrg[e] = pk.z;
        }
        const float4* vs = (const float4*)(vc + (size_t)pk.x * 32);
        const float4* vd = (const float4*)(vc + (size_t)pk.y * 32);
        const float4* vv = (const float4*)(ve + (size_t)pk.z * 32);

        auto put4 = [&](int col, float4 v) {
            int idx = (e * SA + col) * 2;
            *(uint2*)(sm + O_A + idx) = make_uint2(pack_h(v.x, v.y), pack_h(v.z, v.w));
        };
        if (half == 0) {
            #pragma unroll
            for (int q = 0; q < 8; q++) put4(q * 4, vs[q]);
            #pragma unroll
            for (int q = 0; q < 4; q++) put4(32 + q * 4, vd[q]);
        } else {
            #pragma unroll
            for (int q = 0; q < 8; q++) put4(128 + q * 4, vv[q]);
            #pragma unroll
            for (int q = 0; q < 4; q++) put4(48 + q * 4, vd[4 + q]);
        }
    }
    __syncthreads();   // only block-wide barrier

    const int r0 = wid * 16 + g;
    const int ge0 = eBase + r0, ge1 = ge0 + 8;
    const bool ok0 = ge0 < E, ok1 = ge1 < E;

    // ================= GEMM1: X -> H (cols 0..95; ve read via k-remap) ======
    {
        float c[12][4];
        #pragma unroll
        for (int nt = 0; nt < 12; nt++)
            #pragma unroll
            for (int i = 0; i < 4; i++) c[nt][i] = 0.f;

        #pragma unroll
        for (int ks = 0; ks < 6; ks++) {
            int kcol = (ks < 4) ? ks * 16 : 128 + (ks - 4) * 16;
            int b0 = (r0 * SA + kcol + tig * 2) * 2;
            int b1 = ((r0 + 8) * SA + kcol + tig * 2) * 2;
            uint32_t Ah[4];
            Ah[0] = *(uint32_t*)(sm + O_A + b0);
            Ah[1] = *(uint32_t*)(sm + O_A + b1);
            Ah[2] = *(uint32_t*)(sm + O_A + b0 + 16);
            Ah[3] = *(uint32_t*)(sm + O_A + b1 + 16);
            #pragma unroll
            for (int nt = 0; nt < 12; nt++) {
                uint2 bh = __ldg(&gF1[(nt * 6 + ks) * 32 + lane]);
                mma16816(c[nt], Ah, bh);
            }
        }
        __syncwarp();
        #pragma unroll
        for (int nt = 0; nt < 12; nt++) {
            int col = nt * 8 + tig * 2;
            float b0v = __ldg(&bm1[col]), b1v = __ldg(&bm1[col + 1]);
            float h00 = fmaxf(c[nt][0] + b0v, 0.f), h01 = fmaxf(c[nt][1] + b1v, 0.f);
            float h10 = fmaxf(c[nt][2] + b0v, 0.f), h11 = fmaxf(c[nt][3] + b1v, 0.f);
            *(uint32_t*)(sm + O_A + (r0 * SA + col) * 2)       = pack_h(h00, h01);
            *(uint32_t*)(sm + O_A + ((r0 + 8) * SA + col) * 2) = pack_h(h10, h11);
        }
    }
    __syncwarp();

    // ================= GEMM2: H -> F (cols 0..127) ==========================
    {
        float c[17][4];
        #pragma unroll
        for (int nt = 0; nt < 17; nt++)
            #pragma unroll
            for (int i = 0; i < 4; i++) c[nt][i] = 0.f;

        #pragma unroll
        for (int ks = 0; ks < 6; ks++) {
            int b0 = (r0 * SA + ks * 16 + tig * 2) * 2;
            int b1 = ((r0 + 8) * SA + ks * 16 + tig * 2) * 2;
            uint32_t Ah[4];
            Ah[0] = *(uint32_t*)(sm + O_A + b0);
            Ah[1] = *(uint32_t*)(sm + O_A + b1);
            Ah[2] = *(uint32_t*)(sm + O_A + b0 + 16);
            Ah[3] = *(uint32_t*)(sm + O_A + b1 + 16);
            #pragma unroll
            for (int nt = 0; nt < 17; nt++) {
                uint2 bh = __ldg(&gF2[(nt * 6 + ks) * 32 + lane]);
                mma16816(c[nt], Ah, bh);
            }
        }
        if (tig == 0) {
            float b0v = __ldg(&bm2[0]);
            sK[r0]     = 1.f / (1.f + __expf(-(c[16][0] + b0v)));
            sK[r0 + 8] = 1.f / (1.f + __expf(-(c[16][2] + b0v)));
        }
        __syncwarp();
        float kg0 = sK[r0], kg1 = sK[r0 + 8];

        #pragma unroll
        for (int nt = 0; nt < 16; nt++) {
            int col = nt * 8 + tig * 2;
            float b0v = __ldg(&bm2[1 + col]), b1v = __ldg(&bm2[2 + col]);
            float f00 = (c[nt][0] + b0v) * kg0, f01 = (c[nt][1] + b1v) * kg0;
            float f10 = (c[nt][2] + b0v) * kg1, f11 = (c[nt][3] + b1v) * kg1;
            *(uint32_t*)(sm + O_A + (r0 * SA + col) * 2)       = pack_h(f00, f01);
            *(uint32_t*)(sm + O_A + ((r0 + 8) * SA + col) * 2) = pack_h(f10, f11);
        }
    }
    __syncwarp();   // F complete for this warp's 16 rows

    // ================= warp-local segmented reduction (sorted dst) =========
    {
        const int w16 = wid * 16;
        #pragma unroll
        for (int task = 0; task < 2; task++) {
            const int p  = lane + task * 32;
            const int c0 = 2 * p;
            const int grp = c0 >> 5;           // 0=sum,1=max,2=min,3=mean-sum
            float a0 = 0.f, a1 = 0.f;
            int cur = -1;
            bool firstSeg = true;

            auto flush = [&](bool atomic_) {
                if (cur < 0) return;
                size_t base = (size_t)cur * 32;
                if (grp == 0) {
                    if (atomic_) redadd2(&g_s1[base + c0], a0, a1);
                    else *(float2*)&g_s1[base + c0] = make_float2(a0, a1);
                } else if (grp == 1) {
                    unsigned e0 = encf(a0), e1 = encf(a1);
                    if (atomic_) { redmaxu(&g_m2[base + c0 - 32], e0);
                                   redmaxu(&g_m2[base + c0 - 31], e1); }
                    else { g_m2[base + c0 - 32] = e0; g_m2[base + c0 - 31] = e1; }
                } else if (grp == 2) {
                    unsigned e0 = encf(a0), e1 = encf(a1);
                    if (atomic_) { redminu(&g_m3[base + c0 - 64], e0);
                                   redminu(&g_m3[base + c0 - 63], e1); }
                    else { g_m3[base + c0 - 64] = e0; g_m3[base + c0 - 63] = e1; }
                } else {
                    if (atomic_) redadd2(&g_m4[base + c0 - 96], a0, a1);
                    else *(float2*)&g_m4[base + c0 - 96] = make_float2(a0, a1);
                }
            };

            #pragma unroll 4
            for (int r = w16; r < w16 + 16; r++) {
                int d = sDst[r];
                uint32_t uh = *(const uint32_t*)(sm + O_A + (r * SA + c0) * 2);
                __half2 hh = *reinterpret_cast<__half2*>(&uh);
                float f0 = __half2float(__low2half(hh));
                float f1 = __half2float(__high2half(hh));
                if (d != cur) {
                    flush(firstSeg);
                    if (cur >= 0) firstSeg = false;
                    cur = d;
                    a0 = f0; a1 = f1;
                } else if (grp == 1) {
                    a0 = fmaxf(a0, f0); a1 = fmaxf(a1, f1);
                } else if (grp == 2) {
                    a0 = fminf(a0, f0); a1 = fminf(a1, f1);
                } else {
                    a0 += f0; a1 += f1;
                }
            }
            flush(true);
        }
    }

    // ================= GEMM3: [F(0..127)|ve(128..159)] -> out_ve[orig] ======
    {
        float c[4][4];
        #pragma unroll
        for (int nt = 0; nt < 4; nt++)
            #pragma unroll
            for (int i = 0; i < 4; i++) c[nt][i] = 0.f;

        #pragma unroll
        for (int ks = 0; ks < 10; ks++) {
            int b0 = (r0 * SA + ks * 16 + tig * 2) * 2;
            int b1 = ((r0 + 8) * SA + ks * 16 + tig * 2) * 2;
            uint32_t Ah[4];
            Ah[0] = *(uint32_t*)(sm + O_A + b0);
            Ah[1] = *(uint32_t*)(sm + O_A + b1);
            Ah[2] = *(uint32_t*)(sm + O_A + b0 + 16);
            Ah[3] = *(uint32_t*)(sm + O_A + b1 + 16);
            #pragma unroll
            for (int nt = 0; nt < 4; nt++) {
                uint2 bh = __ldg(&gF3[(nt * 10 + ks) * 32 + lane]);
                mma16816(c[nt], Ah, bh);
            }
        }
        int o0 = sOrg[r0], o1 = sOrg[r0 + 8];
        #pragma unroll
        for (int nt = 0; nt < 4; nt++) {
            int col = nt * 8 + tig * 2;
            float b0v = __ldg(&be[col]), b1v = __ldg(&be[col + 1]);
            if (ok0) {
                float2 r = make_float2(c[nt][0] + b0v, c[nt][1] + b1v);
                *(float2*)(out_ve + (size_t)o0 * 32 + col) = r;
            }
            if (ok1) {
                float2 r = make_float2(c[nt][2] + b0v, c[nt][3] + b1v);
                *(float2*)(out_ve + (size_t)o1 * 32 + col) = r;
            }
        }
    }
}

// ================= node update via mma =================
__global__ __launch_bounds__(TPB, 2)
void node_mma_kernel(const float* __restrict__ vc, const float* __restrict__ br,
                     float* __restrict__ out_vc, int N)
{
    extern __shared__ char sm[];
    const int tid  = threadIdx.x;
    const int lane = tid & 31;
    const int wid  = tid >> 5;
    const int g    = lane >> 2;
    const int tig  = lane & 3;
    const int nBase = blockIdx.x * 128;

    {
        int row = tid >> 1, half = tid & 1;
        int n = nBase + row;
        int nc = (n < N) ? n : (N - 1);
        float deg = (float)g_cnt[nc];
        bool has = deg > 0.f;
        float rdeg = 1.f / fmaxf(deg, 1.f);

        auto put4 = [&](int col, float4 v) {
            int idx = (row * SA + col) * 2;
            *(uint2*)(sm + idx) = make_uint2(pack_h(v.x, v.y), pack_h(v.z, v.w));
        };
        for (int q = half; q < 40; q += 2) {
            float4 v;
            if (q < 8) {
                v = ((const float4*)(vc + (size_t)nc * 32))[q];
            } else if (q < 16) {
                v = ((const float4*)(g_s1 + (size_t)nc * 32))[q - 8];
            } else if (q < 24) {
                uint4 u = ((const uint4*)(g_m2 + (size_t)nc * 32))[q - 16];
                v = has ? make_float4(decf(u.x), decf(u.y), decf(u.z), decf(u.w))
                        : make_float4(0.f, 0.f, 0.f, 0.f);
            } else if (q < 32) {
                uint4 u = ((const uint4*)(g_m3 + (size_t)nc * 32))[q - 24];
                v = has ? make_float4(decf(u.x), decf(u.y), decf(u.z), decf(u.w))
                        : make_float4(0.f, 0.f, 0.f, 0.f);
            } else {
                float4 s = ((const float4*)(g_m4 + (size_t)nc * 32))[q - 32];
                v = make_float4(s.x * rdeg, s.y * rdeg, s.z * rdeg, s.w * rdeg);
            }
            put4(q * 4, v);
        }
    }
    __syncthreads();

    const int r0 = wid * 16 + g;
    const int n0 = nBase + r0, n1 = n0 + 8;

    float c[4][4];
    #pragma unroll
    for (int nt = 0; nt < 4; nt++)
        #pragma unroll
        for (int i = 0; i < 4; i++) c[nt][i] = 0.f;

    #pragma unroll
    for (int ks = 0; ks < 10; ks++) {
        int b0 = (r0 * SA + ks * 16 + tig * 2) * 2;
        int b1 = ((r0 + 8) * SA + ks * 16 + tig * 2) * 2;
        uint32_t Ah[4];
        Ah[0] = *(uint32_t*)(sm + b0);
        Ah[1] = *(uint32_t*)(sm + b1);
        Ah[2] = *(uint32_t*)(sm + b0 + 16);
        Ah[3] = *(uint32_t*)(sm + b1 + 16);
        #pragma unroll
        for (int nt = 0; nt < 4; nt++) {
            uint2 bh = __ldg(&gFr[(nt * 10 + ks) * 32 + lane]);
            mma16816(c[nt], Ah, bh);
        }
    }
    #pragma unroll
    for (int nt = 0; nt < 4; nt++) {
        int col = nt * 8 + tig * 2;
        float b0v = __ldg(&br[col]), b1v = __ldg(&br[col + 1]);
        if (n0 < N) {
            float2 r = make_float2(c[nt][0] + b0v, c[nt][1] + b1v);
            *(float2*)(out_vc + (size_t)n0 * 32 + col) = r;
        }
        if (n1 < N) {
            float2 r = make_float2(c[nt][2] + b0v, c[nt][3] + b1v);
            *(float2*)(out_vc + (size_t)n1 * 32 + col) = r;
        }
    }
}

extern "C" void kernel_launch(void* const* d_in, const int* in_sizes, int n_in,
                              void* d_out, int out_size)
{
    const float* vc  = (const float*)d_in[0];
    const float* ve  = (const float*)d_in[1];
    const int*   src = (const int*)d_in[2];
    const int*   dst = (const int*)d_in[3];
    const float* Wm1 = (const float*)d_in[4];
    const float* bm1 = (const float*)d_in[5];
    const float* Wm2 = (const float*)d_in[6];
    const float* bm2 = (const float*)d_in[7];
    const float* Wr  = (const float*)d_in[8];
    const float* br  = (const float*)d_in[9];
    const float* We  = (const float*)d_in[10];
    const float* be  = (const float*)d_in[11];

    int N = in_sizes[0] / 32;
    int E = in_sizes[2];

    float* out_vc = (float*)d_out;
    float* out_ve = out_vc + (size_t)N * 32;

    int nb = (N + 1023) / 1024;

    cudaFuncSetAttribute(edge_kernel, cudaFuncAttributeMaxDynamicSharedMemorySize, SMEMB);
    cudaFuncSetAttribute(node_mma_kernel, cudaFuncAttributeMaxDynamicSharedMemorySize, NSMEMB);

    prep_kernel<<<(254 * 32 + 255) / 256, 256>>>(Wm1, Wm2, We, Wr);
    init_kernel<<<(N * 8 + 255) / 256, 256>>>(N);
    hist_kernel<<<(E + 255) / 256, 256>>>(dst, E);
    scanA_kernel<<<nb, 1024>>>(N);
    scanB_kernel<<<1, 128>>>(nb);
    scanC_kernel<<<nb, 1024>>>(N);
    scat_kernel<<<(E + 255) / 256, 256>>>(src, dst, E);
    edge_kernel<<<(E + BE - 1) / BE, TPB, SMEMB>>>(
        vc, ve, bm1, bm2, be, out_ve, E);
    node_mma_kernel<<<(N + 127) / 128, TPB, NSMEMB>>>(vc, br, out_vc, N);
}